// round 17
// baseline (speedup 1.0000x reference)
#include <cuda_runtime.h>
#include <math.h>

// dims: (1,1,D=160,H=192,W=160), x fastest
#define DW 160
#define DH 192
#define DD 160
#define SLICE (DH*DW)
#define NVOX (DD*SLICE)

#define TX 32
#define TY 8
#define CZ 20
#define SMW (TX+2)
#define SMH (TY+2)
#define NTHREADS (TX*TY)
#define GXD (DW/TX)   // 5
#define GYD (DH/TY)   // 24
#define GZD (DD/CZ)   // 8
#define NBLOCKS (GXD*GYD*GZD)   // 960 = 2 waves of 592
#define FEPS 1e-10f
#define FPI  3.14159265358979f

#define CELLS (SMH*SMW)          // 340
#define BUFBYTES (CELLS*8)       // one slice buffer
#define NSLICEBUF 12             // 4 groups x 3 slices
#define NSTEPS 8                 // 8 x 3 = 24 slices (2 pad, emits guarded)

typedef unsigned long long u64;

// packed (lo,hi) f32x2 helpers — FFMA2/FADD2 only reachable via PTX
__device__ __forceinline__ u64 pk2(float lo, float hi) {
    u64 r; asm("mov.b64 %0, {%1, %2};" : "=l"(r) : "f"(lo), "f"(hi)); return r;
}
__device__ __forceinline__ void upk2(u64 v, float& lo, float& hi) {
    asm("mov.b64 {%0, %1}, %2;" : "=f"(lo), "=f"(hi) : "l"(v));
}
__device__ __forceinline__ u64 fma2(u64 a, u64 b, u64 c) {
    u64 d; asm("fma.rn.f32x2 %0, %1, %2, %3;" : "=l"(d) : "l"(a), "l"(b), "l"(c)); return d;
}
__device__ __forceinline__ u64 add2(u64 a, u64 b) {
    u64 d; asm("add.rn.f32x2 %0, %1, %2;" : "=l"(d) : "l"(a), "l"(b)); return d;
}
#define NEG1P 0xBF800000BF800000ULL   // (-1.f, -1.f)
#define TWOP  0x4000000040000000ULL   // ( 2.f,  2.f)

// 4-byte async copy global -> shared
__device__ __forceinline__ void cpa4(unsigned sdst, const float* gsrc) {
    asm volatile("cp.async.ca.shared.global [%0], [%1], 4;" :: "r"(sdst), "l"(gsrc));
}
#define CP_COMMIT() asm volatile("cp.async.commit_group;" ::: "memory")
#define CP_WAIT2()  asm volatile("cp.async.wait_group 2;" ::: "memory")

__device__ float g_partial[NBLOCKS];
__device__ unsigned int g_count = 0;
__device__ float g_zerosrc[8] = {0,0,0,0,0,0,0,0};

// e = atan(fa/fb) - atan(na/nb) via tan-difference, ONE divide, sign-bit quadrant fix.
__device__ __forceinline__ float atan_diff(float fa, float fb, float na, float nb, float w)
{
    const float num = fmaf(fa, nb, -na * fb);
    const float den = fmaf(fa, na, w);
    const float an = fabsf(num), ad = fabsf(den);
    const float t = __fdividef(fminf(an, ad), fmaxf(an, ad));   // in [0,1]
    const float z = t * t;
    float p = -0.0389929f;                    // deg-7 minimax, max err ~1e-4 rad
    p = fmaf(p, z, 0.1462766f);
    p = fmaf(p, z, -0.3211819f);
    p = fmaf(p, z, 0.9992150f);
    p = p * t;
    float r = (an > ad) ? (1.5707963f - p) : p;
    const unsigned un = __float_as_uint(num);
    const unsigned ud = __float_as_uint(den);
    const unsigned uw = __float_as_uint(w);
    r = __uint_as_float(__float_as_uint(r) | ((un ^ ud) & 0x80000000u));   // sign(num/den)
    // den*w < 0 (sign-bit test) -> add pi with sign(num*w)
    const float c = ((ud ^ uw) & 0x80000000u)
                  ? __uint_as_float(0x40490FDBu | ((un ^ uw) & 0x80000000u)) : 0.f;
    return r + c;
}

__global__ __launch_bounds__(NTHREADS, 4)
void demons_kernel(const float* __restrict__ Mp,
                   const float* __restrict__ Sp,
                   const float* __restrict__ Fp,
                   float* __restrict__ out)
{
    __shared__ u64 sm[NSLICEBUF][SMH][SMW];   // packed (M,S); slice k -> buffer k%12
    __shared__ float warpred[NTHREADS / 32];
    __shared__ bool isLast;

    const int tx = threadIdx.x, ty = threadIdx.y;
    const int tid = ty * TX + tx;
    const int x = blockIdx.x * TX + tx;
    const int y = blockIdx.y * TY + ty;
    const int zbase = blockIdx.z * CZ;
    const int bid = blockIdx.x + GXD * (blockIdx.y + GYD * blockIdx.z);

    // halo mapping (z-invariant): each thread covers <=2 of 340 slots
    const int ly0 = tid / SMW, lx0 = tid - ly0 * SMW;
    const int gy0 = blockIdx.y * TY + ly0 - 1;
    const int gx0 = blockIdx.x * TX + lx0 - 1;
    const bool v0 = ((unsigned)gy0 < (unsigned)DH) && ((unsigned)gx0 < (unsigned)DW);
    const int off0 = v0 ? (gy0 * DW + gx0) : 0;

    const int i1 = tid + NTHREADS;
    const bool has1 = (i1 < CELLS);
    const int ly1 = i1 / SMW, lx1 = i1 - ly1 * SMW;
    const int gy1 = blockIdx.y * TY + ly1 - 1;
    const int gx1 = blockIdx.x * TX + lx1 - 1;
    const bool v1 = has1 && ((unsigned)gy1 < (unsigned)DH) && ((unsigned)gx1 < (unsigned)DW);
    const int off1 = v1 ? (gy1 * DW + gx1) : 0;

    const unsigned sbase = (unsigned)__cvta_generic_to_shared(&sm[0][0][0]);
    const unsigned a0 = sbase + (unsigned)(ly0 * SMW + lx0) * 8u;
    const unsigned a1 = sbase + (unsigned)(ly1 * SMW + lx1) * 8u;
    const float* gz = g_zerosrc;

    // incremental pointers; start at slice zbase-1 (slice index 0)
    const float* pM0 = Mp + (zbase - 1) * SLICE + off0;
    const float* pS0 = Sp + (zbase - 1) * SLICE + off0;
    const float* pM1 = Mp + (zbase - 1) * SLICE + off1;
    const float* pS1 = Sp + (zbase - 1) * SLICE + off1;

    // prologue: 3 groups x 3 slices = slices 0..8 (z = zbase-1 .. zbase+7, upper < DD)
    #pragma unroll
    for (int k = 0; k < 9; ++k) {
        const bool zin = (zbase - 1 + k >= 0);
        const unsigned ab0 = a0 + (unsigned)k * BUFBYTES;
        cpa4(ab0,      (v0 && zin) ? pM0 : gz);
        cpa4(ab0 + 4u, (v0 && zin) ? pS0 : gz);
        if (has1) {
            const unsigned ab1 = a1 + (unsigned)k * BUFBYTES;
            cpa4(ab1,      (v1 && zin) ? pM1 : gz);
            cpa4(ab1 + 4u, (v1 && zin) ? pS1 : gz);
        }
        if (k % 3 == 2) CP_COMMIT();
        pM0 += SLICE; pS0 += SLICE; pM1 += SLICE; pS1 += SLICE;
    }

    // flow: 3 residue sets (J mod 3), each reloads its own z+3 — rotation-free.
    const float* pFb = Fp + y * DW + x;
    int iF0 = (zbase + 1) * SLICE;   // serves J=3,6,...  (z = zbase+1, +4, ...)
    int iF1 = (zbase + 2) * SLICE;   // serves J=4,7,...
    int iF2 = zbase * SLICE;         // serves J=2,5,...
    float F0x = __ldg(pFb + iF0), F0y = __ldg(pFb + iF0 + NVOX), F0z = __ldg(pFb + iF0 + 2 * NVOX);
    iF0 += 3 * SLICE;
    float F1x = __ldg(pFb + iF1), F1y = __ldg(pFb + iF1 + NVOX), F1z = __ldg(pFb + iF1 + 2 * NVOX);
    iF1 += 3 * SLICE;
    float F2x = __ldg(pFb + iF2), F2y = __ldg(pFb + iF2 + NVOX), F2z = __ldg(pFb + iF2 + 2 * NVOX);
    iF2 += 3 * SLICE;

    // packed per-slice responses, register ring of 3; advances 3/step -> period 1 step
    u64 A0, A1, A2, B0, B1, B2, C0, C1, C2, c1r, c2r;
    A0 = A1 = B0 = B1 = C0 = C1 = c1r = 0ULL;
    float acc = 0.f;

// one slice: y-first separable stencil from buffer index RBI, emit for slice index J
// (guarded to J <= CZ+1 — slices 22,23 are pipeline padding) using flow registers
// FX/FY/FZ with reload offset IDX
#define DO_SLICE(RBI, J, FX, FY, FZ, IDX) do {                                                  \
    const u64 av0 = sm[RBI][ty + 0][tx], av1 = sm[RBI][ty + 0][tx + 1], av2 = sm[RBI][ty + 0][tx + 2]; \
    const u64 qv0 = sm[RBI][ty + 1][tx], qv1 = sm[RBI][ty + 1][tx + 1], qv2 = sm[RBI][ty + 1][tx + 2]; \
    const u64 ev0 = sm[RBI][ty + 2][tx], ev1 = sm[RBI][ty + 2][tx + 1], ev2 = sm[RBI][ty + 2][tx + 2]; \
    const u64 ySm0 = fma2(TWOP, qv0, add2(av0, ev0));                                           \
    const u64 yDf0 = fma2(av0, NEG1P, ev0);                                                     \
    const u64 ySm1 = fma2(TWOP, qv1, add2(av1, ev1));                                           \
    const u64 yDf1 = fma2(av1, NEG1P, ev1);                                                     \
    const u64 ySm2 = fma2(TWOP, qv2, add2(av2, ev2));                                           \
    const u64 yDf2 = fma2(av2, NEG1P, ev2);                                                     \
    A2 = fma2(ySm0, NEG1P, ySm2);                 /* smooth_y x diff_x  */                      \
    B2 = fma2(TWOP, yDf1, add2(yDf0, yDf2));      /* diff_y   x smooth_x*/                      \
    C2 = add2(ySm1, add2(ySm0, ySm2));            /* smooth_y x box_x   */                      \
    c2r = qv1;                                                                                  \
    if ((J) >= 2 && (J) <= CZ + 1) {                                                            \
        const u64 Gx = add2(add2(A0, A1), A2);                                                  \
        const u64 Gy = add2(add2(B0, B1), B2);                                                  \
        const u64 Gz = fma2(C0, NEG1P, C2);                                                     \
        float Mcv, Scv; upk2(c1r, Mcv, Scv);                                                    \
        const float Id  = Mcv - Scv;                                                            \
        const float Id2 = fmaf(Id, Id, FEPS);                                                   \
        const u64 d = fma2(Gx, Gx, fma2(Gy, Gy, fma2(Gz, Gz, pk2(Id2, Id2))));                  \
        float dM, dS; upk2(d, dM, dS);                                                          \
        float Mx, Sx; upk2(Gx, Mx, Sx);                                                         \
        float My, Sy; upk2(Gy, My, Sy);                                                         \
        float Mz, Sz; upk2(Gz, Mz, Sz);                                                         \
        const float nx = fmaf(Sx, dM, Mx * dS);                                                 \
        const float ny = fmaf(Sy, dM, My * dS);                                                 \
        const float nz = fmaf(Sz, dM, Mz * dS);                                                 \
        const float FZe = FZ + FEPS;                                                            \
        const float w = FZe * nz;                                                               \
        const float d1 = atan_diff(FX, FZe, nx, nz, w);                                         \
        const float d2 = atan_diff(FY, FZe, ny, nz, w);                                         \
        acc = fmaf(d1, d1, acc);                                                                \
        acc = fmaf(d2, d2, acc);                                                                \
        if ((J) <= CZ - 2) {                                                                    \
            FX = __ldg(pFb + IDX);                                                              \
            FY = __ldg(pFb + IDX + NVOX);                                                       \
            FZ = __ldg(pFb + IDX + 2 * NVOX);                                                   \
            IDX += 3 * SLICE;                                                                   \
        }                                                                                       \
    }                                                                                           \
    A0 = A1; A1 = A2;  B0 = B1; B1 = B2;                                                        \
    C0 = C1; C1 = C2;  c1r = c2r;                                                               \
} while (0)

    #pragma unroll 2
    for (int s = 0; s < NSTEPS; ++s) {          // 8 steps x 3 slices = 24 slices
        // group s complete (2 groups may remain in flight)
        CP_WAIT2();
        __syncthreads();

        // prefetch group s+3 = slices 9+3s..11+3s (z = zbase+8+3s..+10+3s)
        if (s <= NSTEPS - 4) {
            const int wb = ((s + 3) & 3) * 3;
            #pragma unroll
            for (int kk = 0; kk < 3; ++kk) {
                const bool zin = (zbase + 8 + 3 * s + kk < DD);
                const unsigned ab0 = a0 + (unsigned)(wb + kk) * BUFBYTES;
                cpa4(ab0,      (v0 && zin) ? (pM0 + kk * SLICE) : gz);
                cpa4(ab0 + 4u, (v0 && zin) ? (pS0 + kk * SLICE) : gz);
                if (has1) {
                    const unsigned ab1 = a1 + (unsigned)(wb + kk) * BUFBYTES;
                    cpa4(ab1,      (v1 && zin) ? (pM1 + kk * SLICE) : gz);
                    cpa4(ab1 + 4u, (v1 && zin) ? (pS1 + kk * SLICE) : gz);
                }
            }
            pM0 += 3 * SLICE; pS0 += 3 * SLICE; pM1 += 3 * SLICE; pS1 += 3 * SLICE;
        }
        CP_COMMIT();

        const int rb = (s & 3) * 3;             // read buffers rb, rb+1, rb+2
        DO_SLICE(rb,     3 * s,     F0x, F0y, F0z, iF0);
        DO_SLICE(rb + 1, 3 * s + 1, F1x, F1y, F1z, iF1);
        DO_SLICE(rb + 2, 3 * s + 2, F2x, F2y, F2z, iF2);
    }
#undef DO_SLICE

    // block reduction: warp shuffle + smem
    #pragma unroll
    for (int o = 16; o > 0; o >>= 1) acc += __shfl_xor_sync(0xffffffffu, acc, o);
    if ((tid & 31) == 0) warpred[tid >> 5] = acc;
    __syncthreads();
    if (tid == 0) {
        float v = 0.f;
        #pragma unroll
        for (int w = 0; w < NTHREADS / 32; ++w) v += warpred[w];
        g_partial[bid] = v;
        __threadfence();
        const unsigned int c = atomicAdd(&g_count, 1u);
        isLast = (c == (unsigned)(NBLOCKS - 1));
    }
    __syncthreads();

    // last block reduces partials, writes scalar, resets counter
    if (isLast) {
        float s = 0.f;
        for (int i = tid; i < NBLOCKS; i += NTHREADS) s += g_partial[i];
        #pragma unroll
        for (int o = 16; o > 0; o >>= 1) s += __shfl_xor_sync(0xffffffffu, s, o);
        if ((tid & 31) == 0) warpred[tid >> 5] = s;
        __syncthreads();
        if (tid == 0) {
            float t = 0.f;
            #pragma unroll
            for (int w = 0; w < NTHREADS / 32; ++w) t += warpred[w];
            out[0] = t / (float)NVOX;
            g_count = 0u;
        }
    }
}

extern "C" void kernel_launch(void* const* d_in, const int* in_sizes, int n_in,
                              void* d_out, int out_size)
{
    const float* Mp = (const float*)d_in[0];
    const float* Sp = (const float*)d_in[1];
    const float* Fp = (const float*)d_in[2];
    float* out = (float*)d_out;

    dim3 grid(GXD, GYD, GZD);   // (5, 24, 8) = 960 blocks = 2 waves of 592
    dim3 block(TX, TY, 1);      // (32, 8)
    demons_kernel<<<grid, block>>>(Mp, Sp, Fp, out);
}